// round 1
// baseline (speedup 1.0000x reference)
#include <cuda_runtime.h>
#include <cstddef>

#define B_  8
#define C_  64
#define N_  4096
#define N4_ 1024

// Scratch (static device globals; no runtime allocation).
__device__ float g_K [B_*N_*C_];   // (b, n, c)  keys   stage1
__device__ float g_V [B_*N_*C_];   // (b, n, c)  values stage1
__device__ float g_Q [B_*N_*C_];   // (b, n, c)  queries stage2
__device__ float g_qp[B_*N4_*C_];  // (b, j, c)  pooled queries stage1
__device__ float g_o1[B_*N4_*C_];  // (b, j, c)  stage1 output (position-major)
__device__ float g_kp[B_*N4_*C_];  // (b, j, c)  keys   stage2
__device__ float g_vp[B_*N4_*C_];  // (b, j, c)  values stage2

// 64-out GEMV: dst[o] = bias[o] + sum_c w[o][c] * xv[c]   (w, bias in smem)
__device__ __forceinline__ void gemv64(const float* __restrict__ w,
                                       const float* __restrict__ bias,
                                       const float* xv,
                                       float* __restrict__ dst)
{
    #pragma unroll 4
    for (int o = 0; o < 64; o += 4) {
        float a0 = bias[o+0], a1 = bias[o+1], a2 = bias[o+2], a3 = bias[o+3];
        const float4* w0 = (const float4*)(w + (o+0)*64);
        const float4* w1 = (const float4*)(w + (o+1)*64);
        const float4* w2 = (const float4*)(w + (o+2)*64);
        const float4* w3 = (const float4*)(w + (o+3)*64);
        #pragma unroll
        for (int c4 = 0; c4 < 16; c4++) {
            float x0 = xv[4*c4+0], x1 = xv[4*c4+1], x2 = xv[4*c4+2], x3 = xv[4*c4+3];
            float4 a = w0[c4]; a0 += a.x*x0; a0 += a.y*x1; a0 += a.z*x2; a0 += a.w*x3;
            float4 b = w1[c4]; a1 += b.x*x0; a1 += b.y*x1; a1 += b.z*x2; a1 += b.w*x3;
            float4 c = w2[c4]; a2 += c.x*x0; a2 += c.y*x1; a2 += c.z*x2; a2 += c.w*x3;
            float4 d = w3[c4]; a3 += d.x*x0; a3 += d.y*x1; a3 += d.z*x2; a3 += d.w*x3;
        }
        *(float4*)(dst + o) = make_float4(a0, a1, a2, a3);
    }
}

// ---------------- Projection kernels ----------------

// K, V, Q projections from x (B,C,H,W) -> (b, n, c) buffers.
// grid: B*N/128 CTAs of 128 threads. Dynamic smem: (3*4096 + 192) floats.
__global__ void proj3_kernel(const float* __restrict__ x,
                             const float* __restrict__ wK, const float* __restrict__ bK,
                             const float* __restrict__ wV, const float* __restrict__ bV,
                             const float* __restrict__ wQ, const float* __restrict__ bQ)
{
    extern __shared__ float sh[];
    float* sw = sh;            // 3 * 4096
    float* sb = sh + 3*4096;   // 192
    int tid = threadIdx.x;
    for (int i = tid; i < 4096; i += 128) {
        sw[i] = wK[i]; sw[4096 + i] = wV[i]; sw[8192 + i] = wQ[i];
    }
    if (tid < 64) { sb[tid] = bK[tid]; sb[64 + tid] = bV[tid]; sb[128 + tid] = bQ[tid]; }
    __syncthreads();

    int gpos = blockIdx.x * 128 + tid;      // b*4096 + n
    int b = gpos >> 12;
    int n = gpos & (N_ - 1);
    const float* xb = x + (size_t)b * C_ * N_ + n;
    float xv[64];
    #pragma unroll
    for (int c = 0; c < 64; c++) xv[c] = xb[(size_t)c * N_];

    gemv64(sw,        sb,       xv, g_K + (size_t)gpos * 64);
    gemv64(sw + 4096, sb + 64,  xv, g_V + (size_t)gpos * 64);
    gemv64(sw + 8192, sb + 128, xv, g_Q + (size_t)gpos * 64);
}

// Pooled q: qp = w_q @ avg_pool2(x) + b_q   (pool commutes with 1x1 conv).
// grid: B*N4/128 CTAs of 128 threads.
__global__ void proj_pool_q_kernel(const float* __restrict__ x,
                                   const float* __restrict__ wq,
                                   const float* __restrict__ bq)
{
    __shared__ float sw[4096];
    __shared__ float sb[64];
    int tid = threadIdx.x;
    for (int i = tid; i < 4096; i += 128) sw[i] = wq[i];
    if (tid < 64) sb[tid] = bq[tid];
    __syncthreads();

    int gpos = blockIdx.x * 128 + tid;      // b*1024 + j
    int b = gpos >> 10;
    int j = gpos & (N4_ - 1);
    int r = j >> 5, col = j & 31;           // pooled (32x32) coords
    const float* xb = x + (size_t)b * C_ * N_ + r * 128 + col * 2;
    float xv[64];
    #pragma unroll
    for (int c = 0; c < 64; c++) {
        const float* p = xb + (size_t)c * N_;
        xv[c] = 0.25f * (p[0] + p[1] + p[64] + p[65]);
    }
    gemv64(sw, sb, xv, g_qp + (size_t)gpos * 64);
}

// kp, vp projections from stage1 output (position-major).
// grid: B*N4/128 CTAs of 128 threads.
__global__ void proj2_kernel(const float* __restrict__ wk, const float* __restrict__ bk,
                             const float* __restrict__ wv, const float* __restrict__ bv)
{
    __shared__ float sw[2*4096];
    __shared__ float sb[128];
    int tid = threadIdx.x;
    for (int i = tid; i < 4096; i += 128) { sw[i] = wk[i]; sw[4096 + i] = wv[i]; }
    if (tid < 64) { sb[tid] = bk[tid]; sb[64 + tid] = bv[tid]; }
    __syncthreads();

    int gpos = blockIdx.x * 128 + tid;      // b*1024 + j
    const float* src = g_o1 + (size_t)gpos * 64;
    float xv[64];
    #pragma unroll
    for (int c4 = 0; c4 < 16; c4++) {
        float4 v = *(const float4*)(src + 4*c4);
        xv[4*c4+0] = v.x; xv[4*c4+1] = v.y; xv[4*c4+2] = v.z; xv[4*c4+3] = v.w;
    }
    gemv64(sw,        sb,      xv, g_kp + (size_t)gpos * 64);
    gemv64(sw + 4096, sb + 64, xv, g_vp + (size_t)gpos * 64);
}

// ---------------- Fused flash-attention kernel ----------------
// 64-query tile per CTA, 256 threads as 16x16, each thread owns a 4x4 block.
// FINAL=false: stage1 (Q=g_qp 1024q, K/V=g_K/g_V 4096k) -> g_o1 (pos-major)
// FINAL=true : stage2 (Q=g_Q  4096q, K/V=g_kp/g_vp 1024k) -> gamma*out + x -> d_out (B,C,H,W)

template<bool FINAL>
__global__ __launch_bounds__(256, 2)
void attn_kernel(float* __restrict__ outg,
                 const float* __restrict__ xr,
                 const float* __restrict__ gp)
{
    constexpr int NKEY = FINAL ? 1024 : 4096;
    constexpr int NQ   = FINAL ? 4096 : 1024;
    constexpr int W = 65;                    // smem pitch (odd -> <=2-way conflicts)

    extern __shared__ float sh[];
    float* sQ = sh;
    float* sK = sQ + 64*W;
    float* sV = sK + 64*W;
    float* sP = sV + 64*W;

    int tid = threadIdx.x;
    int tx = tid & 15, ty = tid >> 4;
    int b  = blockIdx.y;
    int qt = blockIdx.x;

    const float* Qg = FINAL ? g_Q  : g_qp;
    const float* Kg = FINAL ? g_kp : g_K;
    const float* Vg = FINAL ? g_vp : g_V;

    const float* Qtile = Qg + ((size_t)b * NQ + qt * 64) * 64;
    const float* Kb = Kg + (size_t)b * NKEY * 64;
    const float* Vb = Vg + (size_t)b * NKEY * 64;

    // Load Q tile (64x64) into padded smem.
    for (int i = tid; i < 1024; i += 256) {
        int row = i >> 4, dg = (i & 15) * 4;
        float4 v = *(const float4*)(Qtile + row * 64 + dg);
        float* d = sQ + row * W + dg;
        d[0] = v.x; d[1] = v.y; d[2] = v.z; d[3] = v.w;
    }

    float m[4], l[4], acc[4][4];
    #pragma unroll
    for (int i = 0; i < 4; i++) {
        m[i] = -1e30f; l[i] = 0.f;
        #pragma unroll
        for (int j2 = 0; j2 < 4; j2++) acc[i][j2] = 0.f;
    }
    __syncthreads();

    for (int kt = 0; kt < NKEY / 64; kt++) {
        const float* Kt = Kb + (size_t)kt * 64 * 64;
        const float* Vt = Vb + (size_t)kt * 64 * 64;
        for (int i = tid; i < 1024; i += 256) {
            int row = i >> 4, dg = (i & 15) * 4;
            float4 kv = *(const float4*)(Kt + row * 64 + dg);
            float4 vv = *(const float4*)(Vt + row * 64 + dg);
            float* dk = sK + row * W + dg;
            dk[0] = kv.x; dk[1] = kv.y; dk[2] = kv.z; dk[3] = kv.w;
            float* dv = sV + row * W + dg;
            dv[0] = vv.x; dv[1] = vv.y; dv[2] = vv.z; dv[3] = vv.w;
        }
        __syncthreads();

        // S = Qtile @ Kt^T  (4x4 per thread)
        float s[4][4];
        #pragma unroll
        for (int i = 0; i < 4; i++)
            #pragma unroll
            for (int j2 = 0; j2 < 4; j2++) s[i][j2] = 0.f;

        #pragma unroll 8
        for (int d = 0; d < 64; d++) {
            float qv[4], kv[4];
            #pragma unroll
            for (int i = 0; i < 4; i++)  qv[i]  = sQ[(4*ty + i) * W + d];
            #pragma unroll
            for (int j2 = 0; j2 < 4; j2++) kv[j2] = sK[(4*tx + j2) * W + d];
            #pragma unroll
            for (int i = 0; i < 4; i++)
                #pragma unroll
                for (int j2 = 0; j2 < 4; j2++) s[i][j2] += qv[i] * kv[j2];
        }

        // Online softmax update, write P to smem.
        #pragma unroll
        for (int i = 0; i < 4; i++) {
            float tm = fmaxf(fmaxf(s[i][0], s[i][1]), fmaxf(s[i][2], s[i][3]));
            tm = fmaxf(tm, __shfl_xor_sync(0xffffffffu, tm, 1));
            tm = fmaxf(tm, __shfl_xor_sync(0xffffffffu, tm, 2));
            tm = fmaxf(tm, __shfl_xor_sync(0xffffffffu, tm, 4));
            tm = fmaxf(tm, __shfl_xor_sync(0xffffffffu, tm, 8));
            float mn = fmaxf(m[i], tm);
            float alpha = __expf(m[i] - mn);
            float ps = 0.f;
            #pragma unroll
            for (int j2 = 0; j2 < 4; j2++) {
                float p = __expf(s[i][j2] - mn);
                s[i][j2] = p; ps += p;
            }
            ps += __shfl_xor_sync(0xffffffffu, ps, 1);
            ps += __shfl_xor_sync(0xffffffffu, ps, 2);
            ps += __shfl_xor_sync(0xffffffffu, ps, 4);
            ps += __shfl_xor_sync(0xffffffffu, ps, 8);
            l[i] = l[i] * alpha + ps;
            m[i] = mn;
            #pragma unroll
            for (int j2 = 0; j2 < 4; j2++) acc[i][j2] *= alpha;
            #pragma unroll
            for (int j2 = 0; j2 < 4; j2++) sP[(4*ty + i) * W + 4*tx + j2] = s[i][j2];
        }
        __syncthreads();

        // O += P @ Vt
        #pragma unroll 8
        for (int kk = 0; kk < 64; kk++) {
            float pv[4], vv[4];
            #pragma unroll
            for (int i = 0; i < 4; i++)  pv[i]  = sP[(4*ty + i) * W + kk];
            #pragma unroll
            for (int j2 = 0; j2 < 4; j2++) vv[j2] = sV[kk * W + 4*tx + j2];
            #pragma unroll
            for (int i = 0; i < 4; i++)
                #pragma unroll
                for (int j2 = 0; j2 < 4; j2++) acc[i][j2] += pv[i] * vv[j2];
        }
        __syncthreads();
    }

    if (!FINAL) {
        // Stage1: write (b, j, c) position-major, coalesced float4.
        size_t base = ((size_t)b * N4_ + qt * 64) * 64;
        #pragma unroll
        for (int i = 0; i < 4; i++) {
            float inv = 1.f / l[i];
            *(float4*)(g_o1 + base + (4*ty + i) * 64 + 4*tx) =
                make_float4(acc[i][0]*inv, acc[i][1]*inv, acc[i][2]*inv, acc[i][3]*inv);
        }
    } else {
        // Stage2: transpose via smem, fuse gamma*out2 + x, write (B,C,H,W).
        #pragma unroll
        for (int i = 0; i < 4; i++) {
            float inv = 1.f / l[i];
            #pragma unroll
            for (int j2 = 0; j2 < 4; j2++)
                sP[(4*ty + i) * W + 4*tx + j2] = acc[i][j2] * inv;
        }
        __syncthreads();
        float gamma = gp[0];
        int n0 = qt * 64;
        #pragma unroll 4
        for (int r2 = 0; r2 < 16; r2++) {
            int idx = r2 * 256 + tid;
            int c = idx >> 6, nl = idx & 63;
            size_t ga = ((size_t)b * 64 + c) * (size_t)N_ + n0 + nl;
            outg[ga] = gamma * sP[nl * W + c] + xr[ga];
        }
    }
}

// ---------------- Launch ----------------

extern "C" void kernel_launch(void* const* d_in, const int* in_sizes, int n_in,
                              void* d_out, int out_size)
{
    (void)in_sizes; (void)n_in; (void)out_size;
    const float* x     = (const float*)d_in[0];
    const float* w_q   = (const float*)d_in[1];
    const float* b_q   = (const float*)d_in[2];
    const float* w_K   = (const float*)d_in[3];
    const float* b_K   = (const float*)d_in[4];
    const float* w_V   = (const float*)d_in[5];
    const float* b_V   = (const float*)d_in[6];
    const float* w_Q   = (const float*)d_in[7];
    const float* b_Q   = (const float*)d_in[8];
    const float* w_k   = (const float*)d_in[9];
    const float* b_k   = (const float*)d_in[10];
    const float* w_v   = (const float*)d_in[11];
    const float* b_v   = (const float*)d_in[12];
    const float* gamma = (const float*)d_in[13];
    float* out = (float*)d_out;

    const int proj3_smem = (3*4096 + 192) * 4;   // 49920 B
    const int attn_smem  = 4 * 64 * 65 * 4;      // 66560 B

    cudaFuncSetAttribute(proj3_kernel,      cudaFuncAttributeMaxDynamicSharedMemorySize, proj3_smem);
    cudaFuncSetAttribute(attn_kernel<false>, cudaFuncAttributeMaxDynamicSharedMemorySize, attn_smem);
    cudaFuncSetAttribute(attn_kernel<true>,  cudaFuncAttributeMaxDynamicSharedMemorySize, attn_smem);

    // Projections for stage 1 + stage 2 queries.
    proj3_kernel<<<B_*N_/128, 128, proj3_smem>>>(x, w_K, b_K, w_V, b_V, w_Q, b_Q);
    proj_pool_q_kernel<<<B_*N4_/128, 128>>>(x, w_q, b_q);

    // Stage 1 attention: 1024 pooled queries vs 4096 keys.
    attn_kernel<false><<<dim3(N4_/64, B_), 256, attn_smem>>>(nullptr, nullptr, nullptr);

    // Stage 2 projections from stage1 output.
    proj2_kernel<<<B_*N4_/128, 128>>>(w_k, b_k, w_v, b_v);

    // Stage 2 attention + residual epilogue.
    attn_kernel<true><<<dim3(N_/64, B_), 256, attn_smem>>>(out, x, gamma);
}

// round 5
// speedup vs baseline: 1.0823x; 1.0823x over previous
#include <cuda_runtime.h>
#include <cstddef>

#define B_  8
#define C_  64
#define N_  4096
#define N4_ 1024

// Scratch (static device globals).
__device__ float g_K [B_*C_*N_];   // (b,c,n)  keys   stage1, channel-major
__device__ float g_V [B_*N_*C_];   // (b,n,c)  values stage1, position-major
__device__ float g_Q [B_*C_*N_];   // (b,c,n)  queries stage2, channel-major
__device__ float g_qp[B_*C_*N4_];  // (b,c,j)  pooled queries stage1, channel-major
__device__ float g_o1[B_*N4_*C_];  // (b,j,c)  stage1 output, position-major
__device__ float g_kp[B_*C_*N4_];  // (b,c,j)  keys   stage2, channel-major
__device__ float g_vp[B_*N4_*C_];  // (b,j,c)  values stage2, position-major

typedef unsigned long long u64;

__device__ __forceinline__ u64 pack2(float x, float y) {
    u64 r; asm("mov.b64 %0, {%1,%2};" : "=l"(r) : "f"(x), "f"(y)); return r;
}
__device__ __forceinline__ float2 unpk(u64 v) {
    float2 r; asm("mov.b64 {%0,%1}, %2;" : "=f"(r.x), "=f"(r.y) : "l"(v)); return r;
}
__device__ __forceinline__ void fma2(u64& d, u64 a, u64 b) {
    asm("fma.rn.f32x2 %0, %1, %2, %0;" : "+l"(d) : "l"(a), "l"(b));
}
__device__ __forceinline__ void mul2(u64& d, u64 a) {
    asm("mul.rn.f32x2 %0, %0, %1;" : "+l"(d) : "l"(a));
}

union F4U { float4 v; float f[4]; u64 u[2]; };

// 64-out GEMV with 8 independent accumulator chains (ILP to cover FFMA lat=4).
// OSTRIDE=1 -> contiguous float4 stores; else strided scalar stores (coalesced
// across the warp since consecutive threads own consecutive positions).
template<int OSTRIDE>
__device__ __forceinline__ void gemv64_8(const float* __restrict__ sw,
                                         const float* __restrict__ sb,
                                         const float* xv,
                                         float* __restrict__ dst)
{
    #pragma unroll
    for (int o = 0; o < 64; o += 8) {
        float acc[8];
        #pragma unroll
        for (int k = 0; k < 8; k++) acc[k] = sb[o + k];
        #pragma unroll
        for (int c4 = 0; c4 < 16; c4++) {
            float4 x4 = ((const float4*)xv)[c4];
            #pragma unroll
            for (int k = 0; k < 8; k++) {
                float4 w4 = *(const float4*)(sw + (o + k) * 64 + c4 * 4);
                acc[k] += w4.x * x4.x;
                acc[k] += w4.y * x4.y;
                acc[k] += w4.z * x4.z;
                acc[k] += w4.w * x4.w;
            }
        }
        if (OSTRIDE == 1) {
            *(float4*)(dst + o)     = make_float4(acc[0], acc[1], acc[2], acc[3]);
            *(float4*)(dst + o + 4) = make_float4(acc[4], acc[5], acc[6], acc[7]);
        } else {
            #pragma unroll
            for (int k = 0; k < 8; k++) dst[(size_t)(o + k) * OSTRIDE] = acc[k];
        }
    }
}

// ---------------- Projection kernels ----------------

// K, V, Q projections; gridDim.y selects which (0=K c-major, 1=V n-major, 2=Q c-major).
__global__ void proj3_kernel(const float* __restrict__ x,
                             const float* __restrict__ wK, const float* __restrict__ bK,
                             const float* __restrict__ wV, const float* __restrict__ bV,
                             const float* __restrict__ wQ, const float* __restrict__ bQ)
{
    __shared__ float sw[4096];
    __shared__ float sb[64];
    int which = blockIdx.y;
    const float* wsrc = which == 0 ? wK : (which == 1 ? wV : wQ);
    const float* bsrc = which == 0 ? bK : (which == 1 ? bV : bQ);
    int tid = threadIdx.x;
    for (int i = tid; i < 4096; i += 128) sw[i] = wsrc[i];
    if (tid < 64) sb[tid] = bsrc[tid];
    __syncthreads();

    int gpos = blockIdx.x * 128 + tid;      // b*4096 + n
    int b = gpos >> 12;
    int n = gpos & (N_ - 1);
    const float* xb = x + (size_t)b * C_ * N_ + n;
    float xv[64];
    #pragma unroll
    for (int c = 0; c < 64; c++) xv[c] = xb[(size_t)c * N_];

    if (which == 0)      gemv64_8<N_>(sw, sb, xv, g_K + (size_t)b * C_ * N_ + n);
    else if (which == 1) gemv64_8<1 >(sw, sb, xv, g_V + (size_t)gpos * 64);
    else                 gemv64_8<N_>(sw, sb, xv, g_Q + (size_t)b * C_ * N_ + n);
}

// Pooled q: qp = w_q @ avg_pool2(x) + b_q (pool commutes with 1x1 conv). c-major out.
// grid 128 CTAs x 64 threads.
__global__ void proj_pool_q_kernel(const float* __restrict__ x,
                                   const float* __restrict__ wq,
                                   const float* __restrict__ bq)
{
    __shared__ float sw[4096];
    __shared__ float sb[64];
    int tid = threadIdx.x;
    for (int i = tid; i < 4096; i += 64) sw[i] = wq[i];
    if (tid < 64) sb[tid] = bq[tid];
    __syncthreads();

    int gpos = blockIdx.x * 64 + tid;       // b*1024 + j
    int b = gpos >> 10;
    int j = gpos & (N4_ - 1);
    int r = j >> 5, col = j & 31;
    const float* xb = x + (size_t)b * C_ * N_ + r * 128 + col * 2;
    float xv[64];
    #pragma unroll
    for (int c = 0; c < 64; c++) {
        const float* p = xb + (size_t)c * N_;
        xv[c] = 0.25f * (p[0] + p[1] + p[64] + p[65]);
    }
    gemv64_8<N4_>(sw, sb, xv, g_qp + (size_t)b * C_ * N4_ + j);
}

// kp (c-major), vp (n-major) from stage1 output. gridDim.y selects (0=kp, 1=vp).
__global__ void proj2_kernel(const float* __restrict__ wk, const float* __restrict__ bk,
                             const float* __restrict__ wv, const float* __restrict__ bv)
{
    __shared__ float sw[4096];
    __shared__ float sb[64];
    int which = blockIdx.y;
    const float* wsrc = which ? wv : wk;
    const float* bsrc = which ? bv : bk;
    int tid = threadIdx.x;
    for (int i = tid; i < 4096; i += 128) sw[i] = wsrc[i];
    if (tid < 64) sb[tid] = bsrc[tid];
    __syncthreads();

    int gpos = blockIdx.x * 128 + tid;      // b*1024 + j
    int b = gpos >> 10;
    int j = gpos & (N4_ - 1);
    const float* src = g_o1 + (size_t)gpos * 64;
    float xv[64];
    #pragma unroll
    for (int c4 = 0; c4 < 16; c4++) {
        float4 v = *(const float4*)(src + 4 * c4);
        xv[4*c4+0] = v.x; xv[4*c4+1] = v.y; xv[4*c4+2] = v.z; xv[4*c4+3] = v.w;
    }
    if (which == 0) gemv64_8<N4_>(sw, sb, xv, g_kp + (size_t)b * C_ * N4_ + j);
    else            gemv64_8<1 >(sw, sb, xv, g_vp + (size_t)gpos * 64);
}

// ---------------- Fused flash-attention (fp32x2 packed) ----------------
// 64-query tile per CTA, 256 threads as 16x16, 4x4 per thread; pairs packed
// along the key/channel (j) axis in 64-bit f32x2 registers.
// Q and K are channel-major in gmem -> smem tiles are d-major: sQ[d][q], sK[d][n].

template<bool FINAL>
__global__ __launch_bounds__(256, 2)
void attn_kernel(float* __restrict__ outg,
                 const float* __restrict__ xr,
                 const float* __restrict__ gp)
{
    constexpr int NKEY = FINAL ? 1024 : 4096;
    constexpr int NQ   = FINAL ? 4096 : 1024;
    constexpr int W = 68;                    // pitch: 16B-aligned rows

    extern __shared__ float sh[];
    float* sQ = sh;            // [d][q]
    float* sK = sQ + 64*W;     // [d][n]
    float* sV = sK + 64*W;     // [n][c]
    float* sP = sV + 64*W;     // [q][k]

    int tid = threadIdx.x;
    int tx = tid & 15, ty = tid >> 4;
    int b  = blockIdx.y;
    int qt = blockIdx.x;

    const float* Qb = (FINAL ? g_Q  : g_qp) + (size_t)b * C_ * NQ;
    const float* Kb = (FINAL ? g_kp : g_K ) + (size_t)b * C_ * NKEY;
    const float* Vb = (FINAL ? g_vp : g_V ) + (size_t)b * NKEY * C_;

    // Q tile: sQ[d][ql] <- Qb[d][qt*64+ql]
    for (int i = tid; i < 1024; i += 256) {
        int row = i >> 4, dg = (i & 15) * 4;
        *(float4*)(sQ + row * W + dg) =
            *(const float4*)(Qb + (size_t)row * NQ + qt * 64 + dg);
    }

    float m[4], l[4];
    u64 acc2[4][2];
    #pragma unroll
    for (int i = 0; i < 4; i++) {
        m[i] = -1e30f; l[i] = 0.f;
        acc2[i][0] = 0ull; acc2[i][1] = 0ull;
    }
    __syncthreads();

    for (int kt = 0; kt < NKEY / 64; kt++) {
        for (int i = tid; i < 1024; i += 256) {
            int row = i >> 4, dg = (i & 15) * 4;
            *(float4*)(sK + row * W + dg) =
                *(const float4*)(Kb + (size_t)row * NKEY + kt * 64 + dg);
            *(float4*)(sV + row * W + dg) =
                *(const float4*)(Vb + ((size_t)kt * 64 + row) * 64 + dg);
        }
        __syncthreads();

        // S = Q^T K : per d-step 2x LDS.128 + 4 pack + 8 FFMA2
        u64 s2[4][2];
        #pragma unroll
        for (int i = 0; i < 4; i++) { s2[i][0] = 0ull; s2[i][1] = 0ull; }

        #pragma unroll 4
        for (int d = 0; d < 64; d++) {
            F4U q, k;
            q.v = *(const float4*)(sQ + d * W + 4 * ty);
            k.v = *(const float4*)(sK + d * W + 4 * tx);
            #pragma unroll
            for (int i = 0; i < 4; i++) {
                u64 qq = pack2(q.f[i], q.f[i]);
                fma2(s2[i][0], qq, k.u[0]);
                fma2(s2[i][1], qq, k.u[1]);
            }
        }

        // Online softmax update; write P tile [q][k] (float4, conflict-free).
        #pragma unroll
        for (int i = 0; i < 4; i++) {
            float2 a = unpk(s2[i][0]), c = unpk(s2[i][1]);
            float tm = fmaxf(fmaxf(a.x, a.y), fmaxf(c.x, c.y));
            tm = fmaxf(tm, __shfl_xor_sync(0xffffffffu, tm, 1));
            tm = fmaxf(tm, __shfl_xor_sync(0xffffffffu, tm, 2));
            tm = fmaxf(tm, __shfl_xor_sync(0xffffffffu, tm, 4));
            tm = fmaxf(tm, __shfl_xor_sync(0xffffffffu, tm, 8));
            float mn = fmaxf(m[i], tm);
            float alpha = __expf(m[i] - mn);
            float p0 = __expf(a.x - mn), p1 = __expf(a.y - mn);
            float p2 = __expf(c.x - mn), p3 = __expf(c.y - mn);
            float ps = p0 + p1 + p2 + p3;
            ps += __shfl_xor_sync(0xffffffffu, ps, 1);
            ps += __shfl_xor_sync(0xffffffffu, ps, 2);
            ps += __shfl_xor_sync(0xffffffffu, ps, 4);
            ps += __shfl_xor_sync(0xffffffffu, ps, 8);
            l[i] = l[i] * alpha + ps;
            m[i] = mn;
            u64 al2 = pack2(alpha, alpha);
            mul2(acc2[i][0], al2);
            mul2(acc2[i][1], al2);
            *(float4*)(sP + (4*ty + i) * W + 4*tx) = make_float4(p0, p1, p2, p3);
        }
        __syncthreads();

        // O += P @ V : chunk 4 keys; 8x LDS.128 + 16 pack + 32 FFMA2 per chunk.
        #pragma unroll 2
        for (int kk4 = 0; kk4 < 16; kk4++) {
            F4U p[4], vv[4];
            #pragma unroll
            for (int i = 0; i < 4; i++)
                p[i].v = *(const float4*)(sP + (4*ty + i) * W + 4*kk4);
            #pragma unroll
            for (int t = 0; t < 4; t++)
                vv[t].v = *(const float4*)(sV + (4*kk4 + t) * W + 4*tx);
            #pragma unroll
            for (int i = 0; i < 4; i++) {
                #pragma unroll
                for (int t = 0; t < 4; t++) {
                    u64 pb = pack2(p[i].f[t], p[i].f[t]);
                    fma2(acc2[i][0], pb, vv[t].u[0]);
                    fma2(acc2[i][1], pb, vv[t].u[1]);
                }
            }
        }
        __syncthreads();
    }

    if (!FINAL) {
        // Stage1: write (b, j, c) position-major float4.
        size_t base = ((size_t)b * N4_ + qt * 64) * 64;
        #pragma unroll
        for (int i = 0; i < 4; i++) {
            float inv = 1.f / l[i];
            float2 a = unpk(acc2[i][0]), c = unpk(acc2[i][1]);
            *(float4*)(g_o1 + base + (4*ty + i) * 64 + 4*tx) =
                make_float4(a.x * inv, a.y * inv, c.x * inv, c.y * inv);
        }
    } else {
        // Stage2: transpose via smem, fuse gamma*out2 + x, write (B,C,H,W).
        #pragma unroll
        for (int i = 0; i < 4; i++) {
            float inv = 1.f / l[i];
            float2 a = unpk(acc2[i][0]), c = unpk(acc2[i][1]);
            *(float4*)(sP + (4*ty + i) * W + 4*tx) =
                make_float4(a.x * inv, a.y * inv, c.x * inv, c.y * inv);
        }
        __syncthreads();
        float gamma = gp[0];
        int n0 = qt * 64;
        #pragma unroll 4
        for (int r2 = 0; r2 < 16; r2++) {
            int idx = r2 * 256 + tid;
            int c = idx >> 6, nl = idx & 63;
            size_t ga = ((size_t)b * 64 + c) * (size_t)N_ + n0 + nl;
            outg[ga] = gamma * sP[nl * W + c] + xr[ga];
        }
    }
}

// ---------------- Launch ----------------

extern "C" void kernel_launch(void* const* d_in, const int* in_sizes, int n_in,
                              void* d_out, int out_size)
{
    (void)in_sizes; (void)n_in; (void)out_size;
    const float* x     = (const float*)d_in[0];
    const float* w_q   = (const float*)d_in[1];
    const float* b_q   = (const float*)d_in[2];
    const float* w_K   = (const float*)d_in[3];
    const float* b_K   = (const float*)d_in[4];
    const float* w_V   = (const float*)d_in[5];
    const float* b_V   = (const float*)d_in[6];
    const float* w_Q   = (const float*)d_in[7];
    const float* b_Q   = (const float*)d_in[8];
    const float* w_k   = (const float*)d_in[9];
    const float* b_k   = (const float*)d_in[10];
    const float* w_v   = (const float*)d_in[11];
    const float* b_v   = (const float*)d_in[12];
    const float* gamma = (const float*)d_in[13];
    float* out = (float*)d_out;

    const int attn_smem = 4 * 64 * 68 * 4;   // 69632 B

    cudaFuncSetAttribute(attn_kernel<false>, cudaFuncAttributeMaxDynamicSharedMemorySize, attn_smem);
    cudaFuncSetAttribute(attn_kernel<true>,  cudaFuncAttributeMaxDynamicSharedMemorySize, attn_smem);

    // Projections for stage 1 + stage 2 queries (split by projection for occupancy).
    proj3_kernel<<<dim3(B_*N_/128, 3), 128>>>(x, w_K, b_K, w_V, b_V, w_Q, b_Q);
    proj_pool_q_kernel<<<dim3(B_*N4_/64), 64>>>(x, w_q, b_q);

    // Stage 1 attention: 1024 pooled queries vs 4096 keys.
    attn_kernel<false><<<dim3(N4_/64, B_), 256, attn_smem>>>(nullptr, nullptr, nullptr);

    // Stage 2 projections from stage1 output.
    proj2_kernel<<<dim3(B_*N4_/128, 2), 128>>>(w_k, b_k, w_v, b_v);

    // Stage 2 attention + residual epilogue.
    attn_kernel<true><<<dim3(N_/64, B_), 256, attn_smem>>>(out, x, gamma);
}